// round 7
// baseline (speedup 1.0000x reference)
#include <cuda_runtime.h>
#include <cuda_bf16.h>
#include <cstdint>
#include <math.h>

// ---------------------------------------------------------------------------
// HybridQCNNQLSTM : B=256, S=1024, H=256
//   Stage 1: per-element MLP 1->16->16->12->8->4->4 (tanh) -> 1 (linear)
//   Stage 2: LSTM via mma.sync m16n8k16 bf16 (hi/lo split x3, fp32 acc)
//            8 clusters x 8 CTAs, TWO interleaved batch streams (N=16 each)
//            per-stream mbarrier cluster barriers; cp.async overlapped.
//   out = [cnn_features (B*S) | logits (B)]
// ---------------------------------------------------------------------------

#define BATCH 256
#define SEQ   1024
#define HID   256

// ======================= Stage 1: CNN MLP kernel ===========================

template<int DIN, int DOUT>
__device__ __forceinline__ void layer_tanh(const float* __restrict__ w,
                                           const float* __restrict__ b,
                                           const float* in, float* out) {
#pragma unroll
    for (int o = 0; o < DOUT; ++o) {
        float s = b[o];
#pragma unroll
        for (int i = 0; i < DIN; ++i) s = fmaf(w[o * DIN + i], in[i], s);
        out[o] = tanhf(s);
    }
}

__global__ void __launch_bounds__(256) cnn_kernel(
    const float* __restrict__ x,
    const float* __restrict__ w1, const float* __restrict__ b1,
    const float* __restrict__ w2, const float* __restrict__ b2,
    const float* __restrict__ w3, const float* __restrict__ b3,
    const float* __restrict__ w4, const float* __restrict__ b4,
    const float* __restrict__ w5, const float* __restrict__ b5,
    const float* __restrict__ w6, const float* __restrict__ b6,
    const float* __restrict__ w7, const float* __restrict__ b7,
    float* __restrict__ out)
{
    __shared__ float ws[673];
    const int tid = threadIdx.x;
    {
        const float* srcs[14] = {w1,b1,w2,b2,w3,b3,w4,b4,w5,b5,w6,b6,w7,b7};
        const int    lens[14] = {16,16,256,16,192,12,96,8,32,4,16,4,4,1};
        int off = 0;
        for (int s = 0; s < 14; ++s) {
            for (int i = tid; i < lens[s]; i += 256) ws[off + i] = srcs[s][i];
            off += lens[s];
        }
    }
    __syncthreads();

    const int e = blockIdx.x * 256 + tid;
    float v = x[e];
    float h1[16], h2[16], h3[12], h4[8], h5[4], h6[4];
    layer_tanh<1, 16>(ws + 0,   ws + 16,  &v, h1);
    layer_tanh<16,16>(ws + 32,  ws + 288, h1, h2);
    layer_tanh<16,12>(ws + 304, ws + 496, h2, h3);
    layer_tanh<12, 8>(ws + 508, ws + 604, h3, h4);
    layer_tanh<8,  4>(ws + 612, ws + 644, h4, h5);
    layer_tanh<4,  4>(ws + 648, ws + 664, h5, h6);
    float o = ws[672];
#pragma unroll
    for (int i = 0; i < 4; ++i) o = fmaf(ws[668 + i], h6[i], o);
    out[e] = o;
}

// ======================= Stage 2: LSTM (mma.sync, 2-stream) ================

#define NB           16                     // batches per stream
#define NCLUST       8
#define LSTM_CTAS    64
#define LSTM_THREADS 512

#define ROW_BYTES  1088                     // 16 kc * 64B + 64B pad
#define IMG_BYTES  (NB * ROW_BYTES)         // 17408
#define IMG_U4     (IMG_BYTES / 16)         // 1088

#define RED_STR    18                       // floats per red row (even, 8B ok)

// smem byte offsets
#define BA_OFF     0                        // 17408
#define BB_OFF     17408                    // 17408
#define RED_OFF    34816                    // 2*128*18*4 = 18432
#define WXB_OFF    53248                    // [4][32] f32 = 512
#define BIAS_OFF   53760                    // 512
#define XSA_OFF    54272                    // 64
#define XSB_OFF    54336                    // 64
#define MBARA_OFF  54400                    // 8
#define MBARB_OFF  54408                    // 8
#define SMEM_BYTES 54528

__device__ uint4 g_imgA[2 * NCLUST * IMG_U4];   // ~278 KB
__device__ uint4 g_imgB[2 * NCLUST * IMG_U4];
__device__ float g_hxf32[BATCH * HID];

__device__ __forceinline__ float fast_sigmoid(float v) {
    return __fdividef(1.0f, 1.0f + __expf(-v));
}
__device__ __forceinline__ float fast_tanh(float v) {
    return 1.0f - __fdividef(2.0f, __expf(2.0f * v) + 1.0f);
}
__device__ __forceinline__ uint32_t pack2bf(float lo, float hi) {
    __nv_bfloat162 t = __floats2bfloat162_rn(lo, hi);
    return *(uint32_t*)&t;
}

__device__ __forceinline__ void mma16816(float* c, const uint32_t* a,
                                         uint32_t b0, uint32_t b1) {
    asm volatile(
        "mma.sync.aligned.m16n8k16.row.col.f32.bf16.bf16.f32 "
        "{%0,%1,%2,%3}, {%4,%5,%6,%7}, {%8,%9}, {%0,%1,%2,%3};"
        : "+f"(c[0]), "+f"(c[1]), "+f"(c[2]), "+f"(c[3])
        : "r"(a[0]), "r"(a[1]), "r"(a[2]), "r"(a[3]), "r"(b0), "r"(b1));
}

#define CLUSTER_SYNC_() do { \
    asm volatile("barrier.cluster.arrive.aligned;" ::: "memory"); \
    asm volatile("barrier.cluster.wait.aligned;"   ::: "memory"); \
} while (0)

#define FENCE_CLUSTER_() asm volatile("fence.acq_rel.cluster;" ::: "memory")

#define CP_ASYNC_16(smem_u32, gptr) \
    asm volatile("cp.async.cg.shared.global [%0], [%1], 16;" \
        :: "r"(smem_u32), "l"(gptr) : "memory")
#define CP_ASYNC_COMMIT() asm volatile("cp.async.commit_group;" ::: "memory")
#define CP_ASYNC_WAIT1()  asm volatile("cp.async.wait_group 1;" ::: "memory")
#define CP_ASYNC_WAIT0()  asm volatile("cp.async.wait_group 0;" ::: "memory")

#define MBARRIER_INIT(mbar, cnt) \
    asm volatile("mbarrier.init.shared.b64 [%0], %1;" \
        :: "r"((uint32_t)(mbar)), "r"((uint32_t)(cnt)) : "memory")

// remote arrive on the same smem offset in cluster CTA `rank`
#define MBAR_ARRIVE_REMOTE(mbar, rank) \
    asm volatile("{\n\t.reg .b32 ra;\n\t" \
        "mapa.shared::cluster.u32 ra, %0, %1;\n\t" \
        "mbarrier.arrive.shared::cluster.b64 _, [ra];\n\t}" \
        :: "r"((uint32_t)(mbar)), "r"((uint32_t)(rank)) : "memory")

#define MBAR_WAIT_PARITY(mbar, par) do { \
    uint32_t _m = (uint32_t)(mbar); uint32_t _p = (uint32_t)(par); uint32_t _d; \
    asm volatile("{\n\t.reg .pred p;\n\t" \
        "mbarrier.try_wait.parity.acquire.cta.shared::cta.b64 p, [%1], %2;\n\t" \
        "selp.b32 %0, 1, 0, p;\n\t}" : "=r"(_d) : "r"(_m), "r"(_p) : "memory"); \
    if (!_d) { \
        asm volatile("{\n\t.reg .pred P1;\n\t" \
            "WL_%=:\n\t" \
            "mbarrier.try_wait.parity.acquire.cta.shared::cta.b64 P1, [%0], %1, 0x989680;\n\t" \
            "@P1 bra.uni WD_%=;\n\t" \
            "bra.uni WL_%=;\n\t" \
            "WD_%=:\n\t}" :: "r"(_m), "r"(_p) : "memory"); \
    } \
} while(0)

__global__ void __launch_bounds__(LSTM_THREADS, 1) __cluster_dims__(8, 1, 1)
lstm_kernel(const float* __restrict__ xfeat,
            const float* __restrict__ w_f, const float* __restrict__ b_f,
            const float* __restrict__ w_i, const float* __restrict__ b_i,
            const float* __restrict__ w_g, const float* __restrict__ b_g,
            const float* __restrict__ w_o, const float* __restrict__ b_o,
            const float* __restrict__ w_head, const float* __restrict__ b_head,
            float* __restrict__ logits)
{
    extern __shared__ __align__(16) uint8_t sm8[];
    float* red     = (float*)(sm8 + RED_OFF);
    float* wxb_sm  = (float*)(sm8 + WXB_OFF);
    float* bias_sm = (float*)(sm8 + BIAS_OFF);
    float* xsA     = (float*)(sm8 + XSA_OFF);
    float* xsB     = (float*)(sm8 + XSB_OFF);

    uint32_t smem_u32;
    asm("{ .reg .u64 t; cvta.to.shared.u64 t, %1; cvt.u32.u64 %0, t; }"
        : "=r"(smem_u32) : "l"(sm8));
    const uint32_t mbarA = smem_u32 + MBARA_OFF;
    const uint32_t mbarB = smem_u32 + MBARB_OFF;

    const int tid     = threadIdx.x;
    const int warp    = tid >> 5;
    const int lane    = tid & 31;
    const int ctarank = blockIdx.x & 7;
    const int clust   = blockIdx.x >> 3;
    const int h0      = ctarank * 32;
    const int b0A     = clust * 32;        // stream A batches
    const int b0B     = clust * 32 + NB;   // stream B batches

    const int mrow = warp & 7;     // M tile (16 of 128 gate-rows)
    const int kh   = warp >> 3;    // k half

    const float* Wg[4] = {w_f, w_i, w_g, w_o};
    const float* Bg[4] = {b_f, b_i, b_g, b_o};

    if (tid < 128) {
        int g = tid >> 5, h = tid & 31;
        wxb_sm[g * 32 + h]  = Wg[g][(h0 + h) * 257];
        bias_sm[g * 32 + h] = Bg[g][h0 + h];
    }
    if (tid == 0) { MBARRIER_INIT(mbarA, 8); MBARRIER_INIT(mbarB, 8); }

    // ---- A fragments (this warp's k-half): 8 kc x 4 regs x hi/lo
    uint32_t ahi[32], alo[32];
    {
        const int r0 = mrow * 16 + (lane >> 2);
        const int r1 = r0 + 8;
        const float* row0 = Wg[r0 >> 5] + (h0 + (r0 & 31)) * 257 + 1;
        const float* row1 = Wg[r1 >> 5] + (h0 + (r1 & 31)) * 257 + 1;
        const int kb = (lane & 3) * 2;
#pragma unroll
        for (int kc = 0; kc < 8; ++kc) {
            int k0 = (kh * 8 + kc) * 16 + kb;
            float v00 = row0[k0],     v01 = row0[k0 + 1];
            float v10 = row1[k0],     v11 = row1[k0 + 1];
            float v02 = row0[k0 + 8], v03 = row0[k0 + 9];
            float v12 = row1[k0 + 8], v13 = row1[k0 + 9];
            float h00 = __bfloat162float(__float2bfloat16(v00));
            float h01 = __bfloat162float(__float2bfloat16(v01));
            float h10 = __bfloat162float(__float2bfloat16(v10));
            float h11 = __bfloat162float(__float2bfloat16(v11));
            float h02 = __bfloat162float(__float2bfloat16(v02));
            float h03 = __bfloat162float(__float2bfloat16(v03));
            float h12 = __bfloat162float(__float2bfloat16(v12));
            float h13 = __bfloat162float(__float2bfloat16(v13));
            ahi[kc * 4 + 0] = pack2bf(h00, h01);
            ahi[kc * 4 + 1] = pack2bf(h10, h11);
            ahi[kc * 4 + 2] = pack2bf(h02, h03);
            ahi[kc * 4 + 3] = pack2bf(h12, h13);
            alo[kc * 4 + 0] = pack2bf(v00 - h00, v01 - h01);
            alo[kc * 4 + 1] = pack2bf(v10 - h10, v11 - h11);
            alo[kc * 4 + 2] = pack2bf(v02 - h02, v03 - h03);
            alo[kc * 4 + 3] = pack2bf(v12 - h12, v13 - h13);
        }
    }

    // ---- zero: smem B_A (hx_A(0)=0), global buf0 of both streams
    {
        uint4 z = make_uint4(0, 0, 0, 0);
        uint4* ba = (uint4*)(sm8 + BA_OFF);
        for (int i = tid; i < IMG_U4; i += LSTM_THREADS) ba[i] = z;
        uint4* gA = g_imgA + clust * IMG_U4 + ctarank * (IMG_U4 / 8);
        uint4* gB = g_imgB + clust * IMG_U4 + ctarank * (IMG_U4 / 8);
        for (int i = tid; i < IMG_U4 / 8; i += LSTM_THREADS) { gA[i] = z; gB[i] = z; }
    }
    __syncthreads();
    CLUSTER_SYNC_();   // publishes zeros + mbar inits cluster-wide

    // ---- per-thread constants
    const uint32_t b_lane_off = (uint32_t)((lane >> 2) * ROW_BYTES + (lane & 3) * 16);
    const int ep_b  = tid >> 4;    // 0..31 used as <16 check
    const int ep_hp = tid & 15;    // h-pair
    const bool ep_on = (tid < 256);
    float cxA[2] = {0.f, 0.f};
    float cxB[2] = {0.f, 0.f};

#pragma unroll 1
    for (int t = 0; t < SEQ; ++t) {
        const int par = t & 1;

        // ===== 1. stage B_B <- hx_B(t); overlaps MMA_A =====
        if (t > 0) { MBAR_WAIT_PARITY(mbarB, par ^ 1); FENCE_CLUSTER_(); }
        {
            const uint8_t* src = (const uint8_t*)(g_imgB + (par * NCLUST + clust) * IMG_U4);
            for (int i = tid; i < IMG_U4; i += LSTM_THREADS)
                CP_ASYNC_16(smem_u32 + BB_OFF + i * 16, src + i * 16);
            CP_ASYNC_COMMIT();
        }
        if (tid < NB)                 xsA[tid]      = __ldg(xfeat + (b0A + tid) * SEQ + t);
        else if (tid < 2 * NB)        xsB[tid - NB] = __ldg(xfeat + (b0B + tid - NB) * SEQ + t);

        // ===== 2. stream A compute (B_A already in smem) =====
        {
            float acc[2][4];
#pragma unroll
            for (int nt = 0; nt < 2; ++nt)
#pragma unroll
                for (int j = 0; j < 4; ++j) acc[nt][j] = 0.0f;
#pragma unroll
            for (int nt = 0; nt < 2; ++nt) {
                const uint8_t* bp = sm8 + BA_OFF + nt * 8 * ROW_BYTES + b_lane_off + kh * 512;
#pragma unroll
                for (int kc = 0; kc < 8; ++kc) {
                    uint4 pk = *(const uint4*)(bp + kc * 64);
                    mma16816(acc[nt], ahi + kc * 4, pk.x, pk.y);
                    mma16816(acc[nt], alo + kc * 4, pk.x, pk.y);
                    mma16816(acc[nt], ahi + kc * 4, pk.z, pk.w);
                }
            }
            const int r0 = mrow * 16 + (lane >> 2);
            const int c0 = (lane & 3) * 2;
#pragma unroll
            for (int nt = 0; nt < 2; ++nt) {
                int c = nt * 8 + c0;
                *(float2*)(red + (kh * 128 + r0)     * RED_STR + c) = make_float2(acc[nt][0], acc[nt][1]);
                *(float2*)(red + (kh * 128 + r0 + 8) * RED_STR + c) = make_float2(acc[nt][2], acc[nt][3]);
            }
        }
        __syncthreads();
        if (ep_on) {
            float xb = xsA[ep_b];
            float vout[2];
#pragma unroll
            for (int j = 0; j < 2; ++j) {
                int h = ep_hp * 2 + j;
                float pf = red[(0*32+h)*RED_STR + ep_b] + red[(128 + 0*32+h)*RED_STR + ep_b] + fmaf(wxb_sm[0*32+h], xb, bias_sm[0*32+h]);
                float pi = red[(1*32+h)*RED_STR + ep_b] + red[(128 + 1*32+h)*RED_STR + ep_b] + fmaf(wxb_sm[1*32+h], xb, bias_sm[1*32+h]);
                float pg = red[(2*32+h)*RED_STR + ep_b] + red[(128 + 2*32+h)*RED_STR + ep_b] + fmaf(wxb_sm[2*32+h], xb, bias_sm[2*32+h]);
                float po = red[(3*32+h)*RED_STR + ep_b] + red[(128 + 3*32+h)*RED_STR + ep_b] + fmaf(wxb_sm[3*32+h], xb, bias_sm[3*32+h]);
                float f  = fast_sigmoid(pf);
                float ii = fast_sigmoid(pi);
                float gg = fast_tanh(pg);
                float oo = fast_sigmoid(po);
                cxA[j] = fmaf(f, cxA[j], ii * gg);
                vout[j] = oo * fast_tanh(cxA[j]);
            }
            float f0h = __bfloat162float(__float2bfloat16(vout[0]));
            float f1h = __bfloat162float(__float2bfloat16(vout[1]));
            uint32_t hw = pack2bf(f0h, f1h);
            uint32_t lw = pack2bf(vout[0] - f0h, vout[1] - f1h);
            int kglob = h0 + ep_hp * 2;
            int kc = kglob >> 4, j2 = (kglob & 15) >> 1;
            int c  = (j2 < 4) ? j2 : (j2 - 4);
            int sl = (j2 < 4) ? 0 : 4;
            uint8_t* img = (uint8_t*)(g_imgA + (((par ^ 1) * NCLUST) + clust) * IMG_U4);
            uint8_t* base = img + ep_b * ROW_BYTES + kc * 64 + c * 16 + sl;
            __stcg((unsigned int*)(base),     hw);
            __stcg((unsigned int*)(base + 8), lw);
            if (t == SEQ - 1)
                *(float2*)(g_hxf32 + (b0A + ep_b) * HID + kglob) = make_float2(vout[0], vout[1]);
        }
        FENCE_CLUSTER_();
        __syncthreads();
        if (warp == 0 && lane < 8) MBAR_ARRIVE_REMOTE(mbarA, lane);

        // ===== 3. stage B_A <- hx_A(t+1); overlaps MMA_B =====
        MBAR_WAIT_PARITY(mbarA, par);
        FENCE_CLUSTER_();
        {
            const uint8_t* src = (const uint8_t*)(g_imgA + (((par ^ 1) * NCLUST) + clust) * IMG_U4);
            for (int i = tid; i < IMG_U4; i += LSTM_THREADS)
                CP_ASYNC_16(smem_u32 + BA_OFF + i * 16, src + i * 16);
            CP_ASYNC_COMMIT();
        }

        // ===== 4. B_B landed? =====
        CP_ASYNC_WAIT1();
        __syncthreads();

        // ===== 5. stream B compute =====
        {
            float acc[2][4];
#pragma unroll
            for (int nt = 0; nt < 2; ++nt)
#pragma unroll
                for (int j = 0; j < 4; ++j) acc[nt][j] = 0.0f;
#pragma unroll
            for (int nt = 0; nt < 2; ++nt) {
                const uint8_t* bp = sm8 + BB_OFF + nt * 8 * ROW_BYTES + b_lane_off + kh * 512;
#pragma unroll
                for (int kc = 0; kc < 8; ++kc) {
                    uint4 pk = *(const uint4*)(bp + kc * 64);
                    mma16816(acc[nt], ahi + kc * 4, pk.x, pk.y);
                    mma16816(acc[nt], alo + kc * 4, pk.x, pk.y);
                    mma16816(acc[nt], ahi + kc * 4, pk.z, pk.w);
                }
            }
            const int r0 = mrow * 16 + (lane >> 2);
            const int c0 = (lane & 3) * 2;
#pragma unroll
            for (int nt = 0; nt < 2; ++nt) {
                int c = nt * 8 + c0;
                *(float2*)(red + (kh * 128 + r0)     * RED_STR + c) = make_float2(acc[nt][0], acc[nt][1]);
                *(float2*)(red + (kh * 128 + r0 + 8) * RED_STR + c) = make_float2(acc[nt][2], acc[nt][3]);
            }
        }
        __syncthreads();
        if (ep_on) {
            float xb = xsB[ep_b];
            float vout[2];
#pragma unroll
            for (int j = 0; j < 2; ++j) {
                int h = ep_hp * 2 + j;
                float pf = red[(0*32+h)*RED_STR + ep_b] + red[(128 + 0*32+h)*RED_STR + ep_b] + fmaf(wxb_sm[0*32+h], xb, bias_sm[0*32+h]);
                float pi = red[(1*32+h)*RED_STR + ep_b] + red[(128 + 1*32+h)*RED_STR + ep_b] + fmaf(wxb_sm[1*32+h], xb, bias_sm[1*32+h]);
                float pg = red[(2*32+h)*RED_STR + ep_b] + red[(128 + 2*32+h)*RED_STR + ep_b] + fmaf(wxb_sm[2*32+h], xb, bias_sm[2*32+h]);
                float po = red[(3*32+h)*RED_STR + ep_b] + red[(128 + 3*32+h)*RED_STR + ep_b] + fmaf(wxb_sm[3*32+h], xb, bias_sm[3*32+h]);
                float f  = fast_sigmoid(pf);
                float ii = fast_sigmoid(pi);
                float gg = fast_tanh(pg);
                float oo = fast_sigmoid(po);
                cxB[j] = fmaf(f, cxB[j], ii * gg);
                vout[j] = oo * fast_tanh(cxB[j]);
            }
            float f0h = __bfloat162float(__float2bfloat16(vout[0]));
            float f1h = __bfloat162float(__float2bfloat16(vout[1]));
            uint32_t hw = pack2bf(f0h, f1h);
            uint32_t lw = pack2bf(vout[0] - f0h, vout[1] - f1h);
            int kglob = h0 + ep_hp * 2;
            int kc = kglob >> 4, j2 = (kglob & 15) >> 1;
            int c  = (j2 < 4) ? j2 : (j2 - 4);
            int sl = (j2 < 4) ? 0 : 4;
            uint8_t* img = (uint8_t*)(g_imgB + (((par ^ 1) * NCLUST) + clust) * IMG_U4);
            uint8_t* base = img + ep_b * ROW_BYTES + kc * 64 + c * 16 + sl;
            __stcg((unsigned int*)(base),     hw);
            __stcg((unsigned int*)(base + 8), lw);
            if (t == SEQ - 1)
                *(float2*)(g_hxf32 + (b0B + ep_b) * HID + kglob) = make_float2(vout[0], vout[1]);
        }
        FENCE_CLUSTER_();
        __syncthreads();
        if (warp == 0 && lane < 8) MBAR_ARRIVE_REMOTE(mbarB, lane);

        // ===== 6. B_A landed (for next iteration) =====
        CP_ASYNC_WAIT0();
        __syncthreads();
    }

    CLUSTER_SYNC_();   // final hx of both streams visible cluster-wide

    // ---- head (rank-0 CTA): logits for the cluster's 32 batches
    if (ctarank == 0 && tid < 256) {
        const int bb   = tid >> 3;   // 0..31
        const int part = tid & 7;    // 0..7
        const float* src = g_hxf32 + (clust * 32 + bb) * HID + part * 32;
        float s = 0.0f;
#pragma unroll
        for (int kk = 0; kk < 32; ++kk)
            s = fmaf(src[kk], __ldg(w_head + part * 32 + kk), s);
        s += __shfl_xor_sync(0xffffffffu, s, 4);
        s += __shfl_xor_sync(0xffffffffu, s, 2);
        s += __shfl_xor_sync(0xffffffffu, s, 1);
        if (part == 0) logits[clust * 32 + bb] = s + __ldg(b_head);
    }
}

// ======================= launch ===========================================

extern "C" void kernel_launch(void* const* d_in, const int* in_sizes, int n_in,
                              void* d_out, int out_size)
{
    const float* x      = (const float*)d_in[0];
    const float* w1     = (const float*)d_in[1];
    const float* b1     = (const float*)d_in[2];
    const float* w2     = (const float*)d_in[3];
    const float* b2     = (const float*)d_in[4];
    const float* w3     = (const float*)d_in[5];
    const float* b3     = (const float*)d_in[6];
    const float* w4     = (const float*)d_in[7];
    const float* b4     = (const float*)d_in[8];
    const float* w5     = (const float*)d_in[9];
    const float* b5     = (const float*)d_in[10];
    const float* w6     = (const float*)d_in[11];
    const float* b6     = (const float*)d_in[12];
    const float* w7     = (const float*)d_in[13];
    const float* b7     = (const float*)d_in[14];
    const float* w_f    = (const float*)d_in[15];
    const float* b_f    = (const float*)d_in[16];
    const float* w_i    = (const float*)d_in[17];
    const float* b_i    = (const float*)d_in[18];
    const float* w_g    = (const float*)d_in[19];
    const float* b_g    = (const float*)d_in[20];
    const float* w_o    = (const float*)d_in[21];
    const float* b_o    = (const float*)d_in[22];
    const float* w_head = (const float*)d_in[23];
    const float* b_head = (const float*)d_in[24];

    float* out = (float*)d_out;

    cnn_kernel<<<(BATCH * SEQ) / 256, 256>>>(x, w1, b1, w2, b2, w3, b3, w4, b4,
                                             w5, b5, w6, b6, w7, b7, out);

    cudaFuncSetAttribute(lstm_kernel, cudaFuncAttributeMaxDynamicSharedMemorySize,
                         SMEM_BYTES);
    lstm_kernel<<<LSTM_CTAS, LSTM_THREADS, SMEM_BYTES>>>(
        out, w_f, b_f, w_i, b_i, w_g, b_g, w_o, b_o, w_head, b_head,
        out + BATCH * SEQ);
}